// round 2
// baseline (speedup 1.0000x reference)
#include <cuda_runtime.h>
#include <math.h>

// GWD loss, single fused kernel:
//  - each thread processes 4 rows via aligned float4 loads (5x f4 per tensor)
//  - block reduce -> g_partials
//  - last block (threadfence + atomic counter) reduces partials, writes mean
// Counter self-resets -> deterministic across graph replays.

#define NBLOCKS 1184   // 148 SMs * 8
#define NTHREADS 256

__device__ float g_partials[NBLOCKS];
__device__ unsigned int g_count = 0;

__device__ __forceinline__ float row_loss(
    float xp, float yp, float wp, float hp, float rp,
    float xt, float yt, float wt, float ht, float rt,
    float wgt)
{
    float dx = xp - xt, dy = yp - yt;
    float xyd = dx * dx + dy * dy;

    float cp, sp, ct, st;
    __sincosf(rp, &sp, &cp);
    __sincosf(rt, &st, &ct);

    float w2p = 0.25f * wp * wp, h2p = 0.25f * hp * hp;
    float w2t = 0.25f * wt * wt, h2t = 0.25f * ht * ht;

    float cp2 = cp * cp, sp2 = sp * sp;
    float ct2 = ct * ct, st2 = st * st;

    float a1 = cp2 * w2p + sp2 * h2p;
    float d1 = sp2 * w2p + cp2 * h2p;
    float b1 = cp * sp * (w2p - h2p);

    float a2 = ct2 * w2t + st2 * h2t;
    float d2 = st2 * w2t + ct2 * h2t;
    float b2 = ct * st * (w2t - h2t);

    float trcross = a1 * a2 + 2.0f * b1 * b2 + d1 * d2;
    float prod4   = fabsf(wp * hp * wt * ht);
    float sqdet   = prod4 * 0.0625f;

    float inner = fmaxf(trcross + 2.0f * sqdet, 0.0f);
    float whr   = (w2p + h2p) + (w2t + h2t) - 2.0f * sqrtf(inner);

    float dist  = sqrtf(fmaxf(xyd + whr, 0.0f));
    float scale = sqrtf(sqrtf(prod4));
    dist = log1pf(dist / scale);
    return (1.0f - 1.0f / (1.0f + dist)) * wgt;
}

__global__ __launch_bounds__(NTHREADS)
void gwd_fused_kernel(const float* __restrict__ pred,
                      const float* __restrict__ target,
                      const float* __restrict__ weight,
                      float* __restrict__ out,
                      int n)
{
    const float4* p4 = (const float4*)pred;
    const float4* t4 = (const float4*)target;
    const float4* w4 = (const float4*)weight;

    int ngroups = n >> 2;        // groups of 4 rows = 20 floats = 5 float4
    float acc = 0.0f;

    for (int g = blockIdx.x * NTHREADS + threadIdx.x; g < ngroups;
         g += gridDim.x * NTHREADS)
    {
        // 4 rows: 5 float4 from pred, 5 from target, 1 from weight (all 16B-aligned)
        float4 pa = p4[5 * g + 0], pb = p4[5 * g + 1], pc = p4[5 * g + 2],
               pd = p4[5 * g + 3], pe = p4[5 * g + 4];
        float4 ta = t4[5 * g + 0], tb = t4[5 * g + 1], tc = t4[5 * g + 2],
               td = t4[5 * g + 3], te = t4[5 * g + 4];
        float4 wg = w4[g];

        // row 0: p[0..4] = pa.x pa.y pa.z pa.w pb.x
        acc += row_loss(pa.x, pa.y, pa.z, pa.w, pb.x,
                        ta.x, ta.y, ta.z, ta.w, tb.x, wg.x);
        // row 1: pb.y pb.z pb.w pc.x pc.y
        acc += row_loss(pb.y, pb.z, pb.w, pc.x, pc.y,
                        tb.y, tb.z, tb.w, tc.x, tc.y, wg.y);
        // row 2: pc.z pc.w pd.x pd.y pd.z
        acc += row_loss(pc.z, pc.w, pd.x, pd.y, pd.z,
                        tc.z, tc.w, td.x, td.y, td.z, wg.z);
        // row 3: pd.w pe.x pe.y pe.z pe.w
        acc += row_loss(pd.w, pe.x, pe.y, pe.z, pe.w,
                        td.w, te.x, te.y, te.z, te.w, wg.w);
    }

    // tail rows (n not divisible by 4): handled by first threads of block 0
    int tail_start = ngroups << 2;
    int tail = n - tail_start;
    if (blockIdx.x == 0 && threadIdx.x < tail) {
        int i = tail_start + threadIdx.x;
        const float* p = pred + 5 * (long)i;
        const float* t = target + 5 * (long)i;
        acc += row_loss(p[0], p[1], p[2], p[3], p[4],
                        t[0], t[1], t[2], t[3], t[4], weight[i]);
    }

    // block reduction
    __shared__ float s_warp[NTHREADS / 32];
    for (int off = 16; off > 0; off >>= 1)
        acc += __shfl_down_sync(0xFFFFFFFFu, acc, off);
    int lane = threadIdx.x & 31;
    int wid  = threadIdx.x >> 5;
    if (lane == 0) s_warp[wid] = acc;
    __syncthreads();

    __shared__ bool s_last;
    if (wid == 0) {
        float v = (lane < NTHREADS / 32) ? s_warp[lane] : 0.0f;
        for (int off = 16; off > 0; off >>= 1)
            v += __shfl_down_sync(0xFFFFFFFFu, v, off);
        if (lane == 0) {
            g_partials[blockIdx.x] = v;
            __threadfence();
            unsigned int done = atomicAdd(&g_count, 1u);
            s_last = (done == gridDim.x - 1);
        }
    }
    __syncthreads();

    // last block to finish reduces all partials (deterministic fixed order)
    if (s_last) {
        float v = 0.0f;
        for (int i = threadIdx.x; i < NBLOCKS; i += NTHREADS)
            v += g_partials[i];
        for (int off = 16; off > 0; off >>= 1)
            v += __shfl_down_sync(0xFFFFFFFFu, v, off);
        if (lane == 0) s_warp[wid] = v;
        __syncthreads();
        if (wid == 0) {
            float r = (lane < NTHREADS / 32) ? s_warp[lane] : 0.0f;
            for (int off = 16; off > 0; off >>= 1)
                r += __shfl_down_sync(0xFFFFFFFFu, r, off);
            if (lane == 0) {
                out[0] = r / (float)n;
                g_count = 0;   // reset for next graph replay
            }
        }
    }
}

extern "C" void kernel_launch(void* const* d_in, const int* in_sizes, int n_in,
                              void* d_out, int out_size)
{
    const float* pred   = (const float*)d_in[0];
    const float* target = (const float*)d_in[1];
    const float* weight = (const float*)d_in[2];
    float* out = (float*)d_out;

    int n = in_sizes[2];  // weight has N elements

    gwd_fused_kernel<<<NBLOCKS, NTHREADS>>>(pred, target, weight, out, n);
}